// round 11
// baseline (speedup 1.0000x reference)
#include <cuda_runtime.h>

#define B 32
#define N 3137
#define C 768
#define H 12
#define D 64
#define SCALE 0.125f
#define CHUNKS 18
#define TPAD 36      // 32-col tile + 4 pad (stride ≡ 4 mod 32 -> conflict-free phases)
#define TN 128       // attn tile rows in k_xbar

// ---------------- scratch (static device memory; no allocation) ----------------
__device__ float g_weff[B * H * C];                            // 1.2 MB
__device__ float g_logits[(size_t)B * H * N];                  // 4.8 MB (raw logits)
__device__ float g_max[B * H];                                 // per-(b,h) max logit
__device__ float g_invsum[B * H];                              // per-(b,h) 1/sum(exp)
__device__ float g_partial[(size_t)B * CHUNKS * H * C];        // 21.2 MB
__device__ float g_cls[B * C];

// ---------------- packed f32x2 helpers (Blackwell FFMA2) ----------------
__device__ __forceinline__ unsigned long long pk2(float a, float b) {
    unsigned long long u;
    asm("mov.b64 %0, {%1, %2};" : "=l"(u) : "f"(a), "f"(b));
    return u;
}
__device__ __forceinline__ void upk2(unsigned long long u, float& a, float& b) {
    asm("mov.b64 {%0, %1}, %2;" : "=f"(a), "=f"(b) : "l"(u));
}
__device__ __forceinline__ unsigned long long fma2(unsigned long long a,
                                                   unsigned long long b,
                                                   unsigned long long c) {
    unsigned long long d;
    asm("fma.rn.f32x2 %0, %1, %2, %3;" : "=l"(d) : "l"(a), "l"(b), "l"(c));
    return d;
}

// ---------------- K1: fused q + w_eff for one (h, b) ----------------
__global__ void k_qweff(const float* __restrict__ x, const float* __restrict__ q_w,
                        const float* __restrict__ q_b, const float* __restrict__ kv_w) {
    int h = blockIdx.x, b = blockIdx.y;
    __shared__ float x0[C];
    __shared__ float qh[D];
    const float* xb = x + (size_t)b * N * C;
    for (int c = threadIdx.x; c < C; c += blockDim.x) x0[c] = xb[c];
    __syncthreads();

    int warp = threadIdx.x >> 5, lane = threadIdx.x & 31;
    for (int dl = warp; dl < D; dl += 8) {      // 8 warps x 8 rows
        int j = h * D + dl;
        const float* row = q_w + (size_t)j * C;
        float s = 0.f;
        for (int c = lane * 4; c < C; c += 128) {
            float4 w = *(const float4*)(row + c);
            s += w.x * x0[c] + w.y * x0[c + 1] + w.z * x0[c + 2] + w.w * x0[c + 3];
        }
        #pragma unroll
        for (int o = 16; o; o >>= 1) s += __shfl_xor_sync(0xffffffffu, s, o);
        if (lane == 0) qh[dl] = s + q_b[j];
    }
    __syncthreads();

    for (int c = threadIdx.x; c < C; c += blockDim.x) {
        float s = 0.f;
        const float* base = kv_w + (size_t)(h * D) * C + c;
        #pragma unroll 16
        for (int d = 0; d < D; d++) s += qh[d] * base[(size_t)d * C];
        g_weff[((size_t)b * H + h) * C + c] = s * SCALE;
    }
}

// ---------------- K2: logits[b,h,n] = w_eff[b,h,:] . x[b,n,:] ----------------
// Double-buffered: next step's x tile prefetched into registers (8 float4)
// while current step computes -> LDG latency hidden behind FFMA2 work.
// 3 CTAs/SM (221 KB smem), grid 416 <= 444 slots -> single wave.
__global__ void __launch_bounds__(256, 3) k_logits(const float* __restrict__ x) {
    extern __shared__ float sm[];
    float* weff = sm;  // H*C = 9216 floats
    int b = blockIdx.y;
    for (int i = threadIdx.x; i < H * C; i += 256)
        weff[i] = g_weff[(size_t)b * H * C + i];
    __syncthreads();

    int warp = threadIdx.x >> 5, lane = threadIdx.x & 31;
    float* tile = sm + H * C + warp * (32 * TPAD);
    const float* xb = x + (size_t)b * N * C;
    int nbase = blockIdx.x * 256 + warp * 32;
    int n_lane = nbase + lane;

    unsigned long long acc[H];
    #pragma unroll
    for (int h = 0; h < H; h++) acc[h] = 0ull;

    // prologue: prefetch step 0
    float4 pf[8];
    #pragma unroll
    for (int j = 0; j < 8; j++) {
        int t = lane + j * 32, r = t >> 3, c4 = t & 7;
        int n = nbase + r; if (n > N - 1) n = N - 1;
        pf[j] = *(const float4*)(xb + (size_t)n * C + c4 * 4);
    }

    for (int step = 0; step < 24; step++) {  // 24 steps x 32 cols = 768
        __syncwarp();                        // prior compute done reading tile
        #pragma unroll
        for (int j = 0; j < 8; j++) {
            int t = lane + j * 32, r = t >> 3, c4 = t & 7;
            *(float4*)(tile + r * TPAD + c4 * 4) = pf[j];
        }
        if (step < 23) {                     // prefetch next step (overlaps compute)
            #pragma unroll
            for (int j = 0; j < 8; j++) {
                int t = lane + j * 32, r = t >> 3, c4 = t & 7;
                int n = nbase + r; if (n > N - 1) n = N - 1;
                pf[j] = *(const float4*)(xb + (size_t)n * C + (step + 1) * 32 + c4 * 4);
            }
        }
        __syncwarp();
        #pragma unroll
        for (int c4 = 0; c4 < 8; c4++) {
            ulonglong2 xt = *(const ulonglong2*)(tile + lane * TPAD + c4 * 4);
            int cb = step * 32 + c4 * 4;
            #pragma unroll
            for (int h = 0; h < H; h++) {
                ulonglong2 wt = *(const ulonglong2*)(weff + h * C + cb);  // broadcast
                acc[h] = fma2(wt.x, xt.x, acc[h]);
                acc[h] = fma2(wt.y, xt.y, acc[h]);
            }
        }
    }
    if (n_lane < N) {
        #pragma unroll
        for (int h = 0; h < H; h++) {
            float lo, hi;
            upk2(acc[h], lo, hi);
            g_logits[((size_t)b * H + h) * N + n_lane] = lo + hi;  // coalesced
        }
    }
}

// ---------------- K3: single-pass online max+sum over logits ----------------
__global__ void k_maxsum() {
    int bh = blockIdx.x;
    const float* l = g_logits + (size_t)bh * N;
    __shared__ float red_m[8], red_s[8];
    int tid = threadIdx.x;

    float m = -1e30f, s = 0.f;
    for (int i = tid; i < N; i += 256) {
        float v = l[i];
        if (v > m) { s = s * __expf(m - v) + 1.f; m = v; }
        else       { s += __expf(v - m); }
    }
    #pragma unroll
    for (int o = 16; o; o >>= 1) {
        float m2 = __shfl_xor_sync(0xffffffffu, m, o);
        float s2 = __shfl_xor_sync(0xffffffffu, s, o);
        float M = fmaxf(m, m2);
        s = s * __expf(m - M) + s2 * __expf(m2 - M);
        m = M;
    }
    if ((tid & 31) == 0) { red_m[tid >> 5] = m; red_s[tid >> 5] = s; }
    __syncthreads();
    if (tid == 0) {
        float M = red_m[0];
        for (int i = 1; i < 8; i++) M = fmaxf(M, red_m[i]);
        float S = 0.f;
        for (int i = 0; i < 8; i++) S += red_s[i] * __expf(red_m[i] - M);
        g_max[bh] = M;
        g_invsum[bh] = 1.f / S;
    }
}

// ---------------- K4: xbar partials: sum_n exp(l-m)[b,h,n]*x[b,n,c] ----------------
// 192 threads; thread t owns the float4 column quad [4t, 4t+4) for all 12 heads
// (1 LDG.128 + 12 LDS + 24 FFMA2 per 16 B). CHUNKS=18 -> 576 blocks at
// 4 CTA/SM = ~592 slots: single full wave, ~23 warps/SM.
__global__ void __launch_bounds__(192, 4) k_xbar(const float* __restrict__ x) {
    int chunk = blockIdx.x, b = blockIdx.y;
    __shared__ unsigned long long att2[H * TN];  // 12 KB
    __shared__ float mh[H];
    const int per = (N + CHUNKS - 1) / CHUNKS;   // 175
    int n0 = chunk * per;
    int n1 = min(N, n0 + per);
    const float* xb = x + (size_t)b * N * C;
    int t = threadIdx.x;
    if (t < H) mh[t] = g_max[b * H + t];
    __syncthreads();

    unsigned long long acc0[H], acc1[H];
    #pragma unroll
    for (int h = 0; h < H; h++) { acc0[h] = 0ull; acc1[h] = 0ull; }

    for (int t0 = n0; t0 < n1; t0 += TN) {
        int cnt = min(TN, n1 - t0);
        __syncthreads();
        for (int idx = t; idx < H * TN; idx += 192) {
            int h = idx >> 7, i = idx & (TN - 1);
            float a = (i < cnt) ? __expf(g_logits[((size_t)b * H + h) * N + t0 + i] - mh[h])
                                : 0.f;
            att2[idx] = pk2(a, a);
        }
        __syncthreads();

        int i = 0;
        for (; i + 4 <= cnt; i += 4) {
            // front-batch 4 independent LDG.128s (MLP=4 hides DRAM latency)
            ulonglong2 x0 = *(const ulonglong2*)(xb + (size_t)(t0 + i + 0) * C + 4 * t);
            ulonglong2 x1 = *(const ulonglong2*)(xb + (size_t)(t0 + i + 1) * C + 4 * t);
            ulonglong2 x2 = *(const ulonglong2*)(xb + (size_t)(t0 + i + 2) * C + 4 * t);
            ulonglong2 x3 = *(const ulonglong2*)(xb + (size_t)(t0 + i + 3) * C + 4 * t);
            #pragma unroll
            for (int h = 0; h < H; h++) {
                unsigned long long a = att2[h * TN + i + 0];
                acc0[h] = fma2(a, x0.x, acc0[h]); acc1[h] = fma2(a, x0.y, acc1[h]);
            }
            #pragma unroll
            for (int h = 0; h < H; h++) {
                unsigned long long a = att2[h * TN + i + 1];
                acc0[h] = fma2(a, x1.x, acc0[h]); acc1[h] = fma2(a, x1.y, acc1[h]);
            }
            #pragma unroll
            for (int h = 0; h < H; h++) {
                unsigned long long a = att2[h * TN + i + 2];
                acc0[h] = fma2(a, x2.x, acc0[h]); acc1[h] = fma2(a, x2.y, acc1[h]);
            }
            #pragma unroll
            for (int h = 0; h < H; h++) {
                unsigned long long a = att2[h * TN + i + 3];
                acc0[h] = fma2(a, x3.x, acc0[h]); acc1[h] = fma2(a, x3.y, acc1[h]);
            }
        }
        for (; i < cnt; i++) {
            ulonglong2 xr = *(const ulonglong2*)(xb + (size_t)(t0 + i) * C + 4 * t);
            #pragma unroll
            for (int h = 0; h < H; h++) {
                unsigned long long a = att2[h * TN + i];
                acc0[h] = fma2(a, xr.x, acc0[h]); acc1[h] = fma2(a, xr.y, acc1[h]);
            }
        }
    }
    float* dst = g_partial + ((size_t)b * CHUNKS + chunk) * (size_t)(H * C);
    #pragma unroll
    for (int h = 0; h < H; h++) {
        ulonglong2 v; v.x = acc0[h]; v.y = acc1[h];
        *(ulonglong2*)(dst + h * C + 4 * t) = v;   // STG.128, coalesced
    }
}

// ---------------- K5: reduce partials (x inv_sum) + v-projection ----------------
__global__ void k_cls(const float* __restrict__ kv_w, const float* __restrict__ kv_b) {
    int h = blockIdx.x, b = blockIdx.y;
    __shared__ float xb_sm[C];
    float inv = g_invsum[b * H + h];
    if (threadIdx.x < C / 4) {
        float4 s = make_float4(0.f, 0.f, 0.f, 0.f);
        for (int ch = 0; ch < CHUNKS; ch++) {
            const float4 p = *(const float4*)(g_partial +
                ((size_t)b * CHUNKS + ch) * (size_t)(H * C) + h * C + threadIdx.x * 4);
            s.x += p.x; s.y += p.y; s.z += p.z; s.w += p.w;
        }
        s.x *= inv; s.y *= inv; s.z *= inv; s.w *= inv;
        *(float4*)(xb_sm + threadIdx.x * 4) = s;
    }
    __syncthreads();
    int warp = threadIdx.x >> 5, lane = threadIdx.x & 31;
    for (int d = warp; d < D; d += 8) {
        int j = h * D + d;
        const float* row = kv_w + (size_t)(C + j) * C;  // v-part rows
        float s = 0.f;
        for (int c = lane * 4; c < C; c += 128) {
            float4 w = *(const float4*)(row + c);
            s += w.x * xb_sm[c] + w.y * xb_sm[c + 1] + w.z * xb_sm[c + 2] + w.w * xb_sm[c + 3];
        }
        #pragma unroll
        for (int o = 16; o; o >>= 1) s += __shfl_xor_sync(0xffffffffu, s, o);
        if (lane == 0) g_cls[b * C + j] = s + kv_b[C + j];
    }
}

// ---------------- K6: out[b,:] = cls[b,:] @ proj_w.T + proj_b ----------------
__global__ void k_proj(const float* __restrict__ proj_w, const float* __restrict__ proj_b,
                       float* __restrict__ out) {
    int b = blockIdx.y;
    __shared__ float cls[C];
    for (int c = threadIdx.x; c < C; c += blockDim.x) cls[c] = g_cls[b * C + c];
    __syncthreads();
    int warp = threadIdx.x >> 5, lane = threadIdx.x & 31;
    int j0 = blockIdx.x * 192;
    for (int jj = warp; jj < 192; jj += 8) {
        int j = j0 + jj;
        const float* row = proj_w + (size_t)j * C;
        float s = 0.f;
        for (int c = lane * 4; c < C; c += 128) {
            float4 w = *(const float4*)(row + c);
            s += w.x * cls[c] + w.y * cls[c + 1] + w.z * cls[c + 2] + w.w * cls[c + 3];
        }
        #pragma unroll
        for (int o = 16; o; o >>= 1) s += __shfl_xor_sync(0xffffffffu, s, o);
        if (lane == 0) out[b * C + j] = s + proj_b[j];
    }
}

#define K2_SMEM ((H * C + 8 * 32 * TPAD) * (int)sizeof(float))  // 73,728 B -> 3 CTA/SM

extern "C" void kernel_launch(void* const* d_in, const int* in_sizes, int n_in,
                              void* d_out, int out_size) {
    const float* x      = (const float*)d_in[0];
    const float* kv_w   = (const float*)d_in[1];
    const float* kv_b   = (const float*)d_in[2];
    const float* q_w    = (const float*)d_in[3];
    const float* q_b    = (const float*)d_in[4];
    const float* proj_w = (const float*)d_in[5];
    const float* proj_b = (const float*)d_in[6];
    float* out = (float*)d_out;

    cudaFuncSetAttribute(k_logits, cudaFuncAttributeMaxDynamicSharedMemorySize, K2_SMEM);

    k_qweff<<<dim3(H, B), 256>>>(x, q_w, q_b, kv_w);
    k_logits<<<dim3((N + 255) / 256, B), 256, K2_SMEM>>>(x);
    k_maxsum<<<B * H, 256>>>();
    k_xbar<<<dim3(CHUNKS, B), 192>>>(x);
    k_cls<<<dim3(H, B), 256>>>(kv_w, kv_b);
    k_proj<<<dim3(4, B), 256>>>(proj_w, proj_b, out);
}

// round 12
// speedup vs baseline: 1.2698x; 1.2698x over previous
#include <cuda_runtime.h>

#define B 32
#define N 3137
#define C 768
#define H 12
#define D 64
#define SCALE 0.125f
#define CHUNKS 9
#define TPAD 36      // 32-col tile + 4 pad (stride ≡ 4 mod 32 -> conflict-free phases)
#define TN 128       // attn tile rows in k_xbar
#define H2 6         // head pairs

// ---------------- scratch (static device memory; no allocation) ----------------
__device__ float g_weff[B * H * C];                            // 1.2 MB
__device__ float g_logits[(size_t)B * H * N];                  // 4.8 MB (raw logits)
__device__ float g_max[B * H];                                 // per-(b,h) max logit
__device__ float g_invsum[B * H];                              // per-(b,h) 1/sum(exp)
__device__ float g_partial[(size_t)B * CHUNKS * H * C];        // 10.6 MB
__device__ float g_cls[B * C];

// ---------------- packed f32x2 helpers (Blackwell FFMA2) ----------------
__device__ __forceinline__ unsigned long long pk2(float a, float b) {
    unsigned long long u;
    asm("mov.b64 %0, {%1, %2};" : "=l"(u) : "f"(a), "f"(b));
    return u;
}
__device__ __forceinline__ void upk2(unsigned long long u, float& a, float& b) {
    asm("mov.b64 {%0, %1}, %2;" : "=f"(a), "=f"(b) : "l"(u));
}
__device__ __forceinline__ unsigned long long fma2(unsigned long long a,
                                                   unsigned long long b,
                                                   unsigned long long c) {
    unsigned long long d;
    asm("fma.rn.f32x2 %0, %1, %2, %3;" : "=l"(d) : "l"(a), "l"(b), "l"(c));
    return d;
}

// ---------------- K1: fused q + w_eff for one (h, b) ----------------
__global__ void k_qweff(const float* __restrict__ x, const float* __restrict__ q_w,
                        const float* __restrict__ q_b, const float* __restrict__ kv_w) {
    int h = blockIdx.x, b = blockIdx.y;
    __shared__ float x0[C];
    __shared__ float qh[D];
    const float* xb = x + (size_t)b * N * C;
    for (int c = threadIdx.x; c < C; c += blockDim.x) x0[c] = xb[c];
    __syncthreads();

    int warp = threadIdx.x >> 5, lane = threadIdx.x & 31;
    for (int dl = warp; dl < D; dl += 8) {      // 8 warps x 8 rows
        int j = h * D + dl;
        const float* row = q_w + (size_t)j * C;
        float s = 0.f;
        for (int c = lane * 4; c < C; c += 128) {
            float4 w = *(const float4*)(row + c);
            s += w.x * x0[c] + w.y * x0[c + 1] + w.z * x0[c + 2] + w.w * x0[c + 3];
        }
        #pragma unroll
        for (int o = 16; o; o >>= 1) s += __shfl_xor_sync(0xffffffffu, s, o);
        if (lane == 0) qh[dl] = s + q_b[j];
    }
    __syncthreads();

    for (int c = threadIdx.x; c < C; c += blockDim.x) {
        float s = 0.f;
        const float* base = kv_w + (size_t)(h * D) * C + c;
        #pragma unroll 16
        for (int d = 0; d < D; d++) s += qh[d] * base[(size_t)d * C];
        g_weff[((size_t)b * H + h) * C + c] = s * SCALE;
    }
}

// ---------------- K2: logits[b,h,n] = w_eff[b,h,:] . x[b,n,:] ----------------
// 6 warps; each warp owns 64 rows; each LANE owns TWO rows (r, r+32) so the 12
// per-c4 weight LDS.128 are amortized over 2 rows (48 FFMA2 per 14 LDS).
// grid 9x32 = 288 blocks = 0.97 wave at 2 CTA/SM (92 KB smem). Reg cap 170:
// no spill, staging batches 16 LDG.128 (MLP 16).
__global__ void __launch_bounds__(192, 2) k_logits(const float* __restrict__ x) {
    extern __shared__ float sm[];
    float* weff = sm;  // H*C = 9216 floats
    int b = blockIdx.y;
    for (int i = threadIdx.x; i < H * C; i += 192)
        weff[i] = g_weff[(size_t)b * H * C + i];
    __syncthreads();

    int warp = threadIdx.x >> 5, lane = threadIdx.x & 31;
    float* tile = sm + H * C + warp * (64 * TPAD);
    const float* xb = x + (size_t)b * N * C;
    int base_w = blockIdx.x * 384 + warp * 64;   // this warp's 64-row span
    int r0 = base_w + lane, r1 = r0 + 32;

    unsigned long long acc0[H], acc1[H];
    #pragma unroll
    for (int h = 0; h < H; h++) { acc0[h] = 0ull; acc1[h] = 0ull; }

    for (int step = 0; step < 24; step++) {  // 24 steps x 32 cols = 768
        __syncwarp();                        // prior compute done reading tile
        #pragma unroll
        for (int j = 0; j < 16; j++) {       // 64 rows x 8 float4 / 32 lanes
            int t = lane + j * 32, r = t >> 3, c4 = t & 7;
            int n = base_w + r;
            if (n > N - 1) n = N - 1;
            float4 v = *(const float4*)(xb + (size_t)n * C + step * 32 + c4 * 4);
            *(float4*)(tile + r * TPAD + c4 * 4) = v;
        }
        __syncwarp();
        #pragma unroll
        for (int c4 = 0; c4 < 8; c4++) {
            ulonglong2 xt0 = *(const ulonglong2*)(tile + lane * TPAD + c4 * 4);
            ulonglong2 xt1 = *(const ulonglong2*)(tile + (lane + 32) * TPAD + c4 * 4);
            int cb = step * 32 + c4 * 4;
            #pragma unroll
            for (int h = 0; h < H; h++) {
                ulonglong2 wt = *(const ulonglong2*)(weff + h * C + cb);  // broadcast
                acc0[h] = fma2(wt.x, xt0.x, acc0[h]);
                acc0[h] = fma2(wt.y, xt0.y, acc0[h]);
                acc1[h] = fma2(wt.x, xt1.x, acc1[h]);
                acc1[h] = fma2(wt.y, xt1.y, acc1[h]);
            }
        }
    }
    #pragma unroll
    for (int h = 0; h < H; h++) {
        float lo, hi;
        if (r0 < N) {
            upk2(acc0[h], lo, hi);
            g_logits[((size_t)b * H + h) * N + r0] = lo + hi;  // coalesced
        }
        if (r1 < N) {
            upk2(acc1[h], lo, hi);
            g_logits[((size_t)b * H + h) * N + r1] = lo + hi;
        }
    }
}

// ---------------- K3: single-pass online max+sum over logits ----------------
__global__ void k_maxsum() {
    int bh = blockIdx.x;
    const float* l = g_logits + (size_t)bh * N;
    __shared__ float red_m[8], red_s[8];
    int tid = threadIdx.x;

    float m = -1e30f, s = 0.f;
    for (int i = tid; i < N; i += 256) {
        float v = l[i];
        if (v > m) { s = s * __expf(m - v) + 1.f; m = v; }
        else       { s += __expf(v - m); }
    }
    #pragma unroll
    for (int o = 16; o; o >>= 1) {
        float m2 = __shfl_xor_sync(0xffffffffu, m, o);
        float s2 = __shfl_xor_sync(0xffffffffu, s, o);
        float M = fmaxf(m, m2);
        s = s * __expf(m - M) + s2 * __expf(m2 - M);
        m = M;
    }
    if ((tid & 31) == 0) { red_m[tid >> 5] = m; red_s[tid >> 5] = s; }
    __syncthreads();
    if (tid == 0) {
        float M = red_m[0];
        for (int i = 1; i < 8; i++) M = fmaxf(M, red_m[i]);
        float S = 0.f;
        for (int i = 0; i < 8; i++) S += red_s[i] * __expf(red_m[i] - M);
        g_max[bh] = M;
        g_invsum[bh] = 1.f / S;
    }
}

// ---------------- K4: xbar partials: sum_n exp(l-m)[b,h,n]*x[b,n,c] ----------------
// 384 threads; thread t owns col pair (2t, 2t+1) for all 12 heads. Attention
// weights packed 2-heads-per-float4 in smem: per row 6 LDS.128 (broadcast)
// instead of 12 LDS.64 -> 34% fewer issued instructions per byte.
// CHUNKS=9 -> 288 blocks = 0.97 wave at 2 CTA/SM.
__global__ void __launch_bounds__(384, 2) k_xbar(const float* __restrict__ x) {
    int chunk = blockIdx.x, b = blockIdx.y;
    __shared__ float4 att4[TN * H2];   // [i][h2]: {a(2h2),a(2h2),a(2h2+1),a(2h2+1)}, 12 KB
    __shared__ float mh[H];
    const int per = (N + CHUNKS - 1) / CHUNKS;   // 349
    int n0 = chunk * per;
    int n1 = min(N, n0 + per);
    const float* xb = x + (size_t)b * N * C;
    int t = threadIdx.x;
    if (t < H) mh[t] = g_max[b * H + t];
    __syncthreads();

    unsigned long long acc[H];
    #pragma unroll
    for (int h = 0; h < H; h++) acc[h] = 0ull;

    for (int t0 = n0; t0 < n1; t0 += TN) {
        int cnt = min(TN, n1 - t0);
        __syncthreads();
        // stage packed exp weights: idx -> (h2 = idx/TN, i = idx%TN), i fastest
        // so the two g_logits reads per thread are coalesced over i.
        #pragma unroll
        for (int rep = 0; rep < 2; rep++) {          // H2*TN = 768 = 2*384
            int idx = t + rep * 384;
            int h2 = idx / TN, i = idx & (TN - 1);
            float a0 = 0.f, a1 = 0.f;
            if (i < cnt) {
                a0 = __expf(g_logits[((size_t)b * H + 2 * h2) * N + t0 + i] - mh[2 * h2]);
                a1 = __expf(g_logits[((size_t)b * H + 2 * h2 + 1) * N + t0 + i] - mh[2 * h2 + 1]);
            }
            att4[i * H2 + h2] = make_float4(a0, a0, a1, a1);
        }
        __syncthreads();

        int i = 0;
        for (; i + 4 <= cnt; i += 4) {
            // front-batch 4 independent LDG.64s (MLP=4 hides DRAM latency)
            unsigned long long x0 = *(const unsigned long long*)(xb + (size_t)(t0 + i + 0) * C + 2 * t);
            unsigned long long x1 = *(const unsigned long long*)(xb + (size_t)(t0 + i + 1) * C + 2 * t);
            unsigned long long x2 = *(const unsigned long long*)(xb + (size_t)(t0 + i + 2) * C + 2 * t);
            unsigned long long x3 = *(const unsigned long long*)(xb + (size_t)(t0 + i + 3) * C + 2 * t);
            #pragma unroll
            for (int h2 = 0; h2 < H2; h2++) {
                ulonglong2 a = *(const ulonglong2*)(att4 + (i + 0) * H2 + h2);
                acc[2 * h2]     = fma2(a.x, x0, acc[2 * h2]);
                acc[2 * h2 + 1] = fma2(a.y, x0, acc[2 * h2 + 1]);
            }
            #pragma unroll
            for (int h2 = 0; h2 < H2; h2++) {
                ulonglong2 a = *(const ulonglong2*)(att4 + (i + 1) * H2 + h2);
                acc[2 * h2]     = fma2(a.x, x1, acc[2 * h2]);
                acc[2 * h2 + 1] = fma2(a.y, x1, acc[2 * h2 + 1]);
            }
            #pragma unroll
            for (int h2 = 0; h2 < H2; h2++) {
                ulonglong2 a = *(const ulonglong2*)(att4 + (i + 2) * H2 + h2);
                acc[2 * h2]     = fma2(a.x, x2, acc[2 * h2]);
                acc[2 * h2 + 1] = fma2(a.y, x2, acc[2 * h2 + 1]);
            }
            #pragma unroll
            for (int h2 = 0; h2 < H2; h2++) {
                ulonglong2 a = *(const ulonglong2*)(att4 + (i + 3) * H2 + h2);
                acc[2 * h2]     = fma2(a.x, x3, acc[2 * h2]);
                acc[2 * h2 + 1] = fma2(a.y, x3, acc[2 * h2 + 1]);
            }
        }
        for (; i < cnt; i++) {
            unsigned long long xr = *(const unsigned long long*)(xb + (size_t)(t0 + i) * C + 2 * t);
            #pragma unroll
            for (int h2 = 0; h2 < H2; h2++) {
                ulonglong2 a = *(const ulonglong2*)(att4 + i * H2 + h2);
                acc[2 * h2]     = fma2(a.x, xr, acc[2 * h2]);
                acc[2 * h2 + 1] = fma2(a.y, xr, acc[2 * h2 + 1]);
            }
        }
    }
    float* dst = g_partial + ((size_t)b * CHUNKS + chunk) * (size_t)(H * C);
    #pragma unroll
    for (int h = 0; h < H; h++)
        *(unsigned long long*)(dst + h * C + 2 * t) = acc[h];   // coalesced
}

// ---------------- K5: reduce partials (x inv_sum) + v-projection ----------------
__global__ void k_cls(const float* __restrict__ kv_w, const float* __restrict__ kv_b) {
    int h = blockIdx.x, b = blockIdx.y;
    __shared__ float xb_sm[C];
    float inv = g_invsum[b * H + h];
    if (threadIdx.x < C / 4) {
        float4 s = make_float4(0.f, 0.f, 0.f, 0.f);
        for (int ch = 0; ch < CHUNKS; ch++) {
            const float4 p = *(const float4*)(g_partial +
                ((size_t)b * CHUNKS + ch) * (size_t)(H * C) + h * C + threadIdx.x * 4);
            s.x += p.x; s.y += p.y; s.z += p.z; s.w += p.w;
        }
        s.x *= inv; s.y *= inv; s.z *= inv; s.w *= inv;
        *(float4*)(xb_sm + threadIdx.x * 4) = s;
    }
    __syncthreads();
    int warp = threadIdx.x >> 5, lane = threadIdx.x & 31;
    for (int d = warp; d < D; d += 8) {
        int j = h * D + d;
        const float* row = kv_w + (size_t)(C + j) * C;  // v-part rows
        float s = 0.f;
        for (int c = lane * 4; c < C; c += 128) {
            float4 w = *(const float4*)(row + c);
            s += w.x * xb_sm[c] + w.y * xb_sm[c + 1] + w.z * xb_sm[c + 2] + w.w * xb_sm[c + 3];
        }
        #pragma unroll
        for (int o = 16; o; o >>= 1) s += __shfl_xor_sync(0xffffffffu, s, o);
        if (lane == 0) g_cls[b * C + j] = s + kv_b[C + j];
    }
}

// ---------------- K6: out[b,:] = cls[b,:] @ proj_w.T + proj_b ----------------
__global__ void k_proj(const float* __restrict__ proj_w, const float* __restrict__ proj_b,
                       float* __restrict__ out) {
    int b = blockIdx.y;
    __shared__ float cls[C];
    for (int c = threadIdx.x; c < C; c += blockDim.x) cls[c] = g_cls[b * C + c];
    __syncthreads();
    int warp = threadIdx.x >> 5, lane = threadIdx.x & 31;
    int j0 = blockIdx.x * 192;
    for (int jj = warp; jj < 192; jj += 8) {
        int j = j0 + jj;
        const float* row = proj_w + (size_t)j * C;
        float s = 0.f;
        for (int c = lane * 4; c < C; c += 128) {
            float4 w = *(const float4*)(row + c);
            s += w.x * cls[c] + w.y * cls[c + 1] + w.z * cls[c + 2] + w.w * cls[c + 3];
        }
        #pragma unroll
        for (int o = 16; o; o >>= 1) s += __shfl_xor_sync(0xffffffffu, s, o);
        if (lane == 0) out[b * C + j] = s + proj_b[j];
    }
}

#define K2_SMEM ((H * C + 6 * 64 * TPAD) * (int)sizeof(float))  // 92,160 B -> 2 CTA/SM

extern "C" void kernel_launch(void* const* d_in, const int* in_sizes, int n_in,
                              void* d_out, int out_size) {
    const float* x      = (const float*)d_in[0];
    const float* kv_w   = (const float*)d_in[1];
    const float* kv_b   = (const float*)d_in[2];
    const float* q_w    = (const float*)d_in[3];
    const float* q_b    = (const float*)d_in[4];
    const float* proj_w = (const float*)d_in[5];
    const float* proj_b = (const float*)d_in[6];
    float* out = (float*)d_out;

    cudaFuncSetAttribute(k_logits, cudaFuncAttributeMaxDynamicSharedMemorySize, K2_SMEM);

    k_qweff<<<dim3(H, B), 256>>>(x, q_w, q_b, kv_w);
    k_logits<<<dim3((N + 383) / 384, B), 192, K2_SMEM>>>(x);
    k_maxsum<<<B * H, 256>>>();
    k_xbar<<<dim3(CHUNKS, B), 384>>>(x);
    k_cls<<<dim3(H, B), 256>>>(kv_w, kv_b);
    k_proj<<<dim3(4, B), 256>>>(proj_w, proj_b, out);
}